// round 14
// baseline (speedup 1.0000x reference)
#include <cuda_runtime.h>
#include <cuda_fp16.h>
#include <cstdint>
#include <cfloat>

// Shapes fixed by dataset: T=32768 tokens, K=4096 codes, D=256.
#define T_TOK 32768
#define K_COD 4096
#define D_DIM 256
#define EPS_GAP 0.004f
#define KSCALE 32768.0f          // key resolution = 1/KSCALE
#define KBIG   134217728.0f      // KSCALE * 4096 = 2^27

// Main kernel: CTA = 256 tokens x full K, 512 threads, 16 warps = 4(M) x 4(N),
// warp tile 64 tok x 32 codes. N chunk 128 codes, k-stage 64 (4 HMMA k16),
// 128 stages unrolled as 32 chunks x (2 groups of 2 stages). Grid 128.
#define A_OFF   0        // A frags fp16: [mtile16][ktile16][lane] uint4 = 128KB
#define B_OFF   131072   // ring: 4 stages x 16KB; slots 0/1 reused for keys
#define ESQ_OFF 196608   // cesc = (16 - esq)*2^27, 16KB
#define SMEM_BYTES 212992

__device__ uint4  g_bt[(size_t)128 * 1024];   // 2MB packed B fragments
__device__ float  g_esq[K_COD];               // ||e||^2 (for exact rescore)
__device__ float  g_cesc[K_COD];              // (16 - ||e||^2) * 2^27
__device__ uint32_t g_ckey[(size_t)T_TOK * 32];  // 4MB candidate keys

static __device__ __forceinline__ uint32_t smem_u32(const void* p) {
    uint32_t a;
    asm("{ .reg .u64 t; cvta.to.shared.u64 t, %1; cvt.u32.u64 %0, t; }"
        : "=r"(a) : "l"(p));
    return a;
}
static __device__ __forceinline__ void cp16(uint32_t dst, const void* src) {
    asm volatile("cp.async.cg.shared.global [%0], [%1], 16;"
                 :: "r"(dst), "l"(__cvta_generic_to_global(src)) : "memory");
}
#define CP_COMMIT() asm volatile("cp.async.commit_group;" ::: "memory")
#define CP_WAIT(n)  asm volatile("cp.async.wait_group %0;" :: "n"(n) : "memory")

static __device__ __forceinline__ void mma16(float& d0, float& d1, float& d2, float& d3,
                                             uint4 a, uint32_t b0, uint32_t b1) {
    asm volatile(
        "mma.sync.aligned.m16n8k16.row.col.f32.f16.f16.f32 "
        "{%0,%1,%2,%3}, {%4,%5,%6,%7}, {%8,%9}, {%0,%1,%2,%3};"
        : "+f"(d0), "+f"(d1), "+f"(d2), "+f"(d3)
        : "r"(a.x), "r"(a.y), "r"(a.z), "r"(a.w), "r"(b0), "r"(b1));
}
static __device__ __forceinline__ uint32_t h2pack(float a, float b) {
    __half2 h = __floats2half2_rn(a, b);
    return *(uint32_t*)&h;
}

// ---------------------------------------------------------------------------
// Fused prep: pack embed -> fp16 B fragments AND per-row esq/cesc.
__global__ void prep_kernel(const float* __restrict__ embed) {
    const int tid = threadIdx.x, lane = tid & 31, wrp = tid >> 5;

    {   // pack_b: u = [stage(128)][kk(4)][np(8)][lane(32)]
        uint32_t u = blockIdx.x * 256 + tid;
        int s = u >> 10, r = u & 1023;
        int kk = r >> 8, np = (r >> 5) & 7, ln = r & 31;
        int nc = s >> 2, q4 = s & 3;
        int k = q4 * 64 + kk * 16 + (ln & 3) * 2;
        int n0 = nc * 128 + np * 16 + (ln >> 2);
        const float* e0 = embed + (size_t)n0 * D_DIM + k;
        const float* e1 = e0 + 8 * D_DIM;
        uint4 q;
        q.x = h2pack(e0[0], e0[1]);
        q.y = h2pack(e0[8], e0[9]);
        q.z = h2pack(e1[0], e1[1]);
        q.w = h2pack(e1[8], e1[9]);
        g_bt[u] = q;
    }

    {   // esq: warp per code row, coalesced, deterministic shfl tree
        const int k = blockIdx.x * 8 + wrp;
        const float* row = embed + (size_t)k * D_DIM;
        float s = 0.f;
#pragma unroll
        for (int j = 0; j < 8; ++j) {
            float v = row[lane + 32 * j];
            s = __fadd_rn(s, __fmul_rn(v, v));
        }
#pragma unroll
        for (int off = 16; off > 0; off >>= 1)
            s = __fadd_rn(s, __shfl_xor_sync(0xffffffffu, s, off));
        if (lane == 0) {
            g_esq[k] = s;
            g_cesc[k] = (16.0f - s) * KBIG;
        }
    }
}

// ---------------------------------------------------------------------------
// Two k-stages with compile-time ring slots and ktile bases.
template<int SLOT0, int KT0>
static __device__ __forceinline__ void two_stages(
    const char* sm, int warpM, int warpN, int lane, float (&acc)[4][4][4]) {
#pragma unroll
    for (int hs = 0; hs < 2; ++hs) {
        const char* bbuf = sm + B_OFF + (SLOT0 + hs) * 16384;
#pragma unroll
        for (int kk = 0; kk < 4; ++kk) {
            const int ktile = KT0 + hs * 4 + kk;
            uint4 a[4];
#pragma unroll
            for (int mt = 0; mt < 4; ++mt)
                a[mt] = *(const uint4*)(sm + A_OFF +
                        (size_t)(((warpM * 4 + mt) * 16 + ktile) * 32 + lane) * 16);
#pragma unroll
            for (int npl = 0; npl < 2; ++npl) {
                uint4 bq = *(const uint4*)(bbuf +
                           (size_t)((kk * 8 + warpN * 2 + npl) * 32 + lane) * 16);
                int ne = 2 * npl, no = 2 * npl + 1;
#pragma unroll
                for (int mt = 0; mt < 4; ++mt) {
                    mma16(acc[mt][ne][0], acc[mt][ne][1], acc[mt][ne][2], acc[mt][ne][3],
                          a[mt], bq.x, bq.y);
                    mma16(acc[mt][no][0], acc[mt][no][1], acc[mt][no][2], acc[mt][no][3],
                          a[mt], bq.z, bq.w);
                }
            }
        }
    }
}

// Prefetch one 16KB B stage into a static ring slot (one commit group).
static __device__ __forceinline__ void prefetch_stage(uint32_t sb, int tid, int g,
                                                      uint32_t slotoff) {
    const uint4* bs = g_bt + (size_t)g * 1024;
#pragma unroll
    for (int i = 0; i < 2; ++i)
        cp16(sb + B_OFF + slotoff + (uint32_t)(i * 512 + tid) * 16, bs + i * 512 + tid);
    CP_COMMIT();
}

// ---------------------------------------------------------------------------
// Main: A-pack prologue + fp16 GEMM (static-slot pipeline) + key top-2 +
// confident-token gather tail.
__global__ __launch_bounds__(512, 1) void vq_mma_kernel(const float* __restrict__ x,
                                                        const float* __restrict__ embed,
                                                        float* __restrict__ out_q,
                                                        float* __restrict__ out_i) {
    extern __shared__ char sm[];
    const uint32_t sb = smem_u32(sm);
    const int tid = threadIdx.x, lane = tid & 31, wid = tid >> 5;
    const int warpM = wid & 3, warpN = wid >> 2;   // 4 x 4
    const int cta = blockIdx.x;
    const int t0 = cta * 256;

    // ---- Prologue: cesc + B stages 0,1 (async), then A conversion ----
    {
        const uint4* es = (const uint4*)g_cesc;
#pragma unroll
        for (int i = 0; i < 2; ++i)
            cp16(sb + ESQ_OFF + (uint32_t)(i * 512 + tid) * 16, es + i * 512 + tid);
    }
    prefetch_stage(sb, tid, 0, 0);
    prefetch_stage(sb, tid, 1, 16384);

    // A: fp16 fragments straight from global x.
#pragma unroll
    for (int it = 0; it < 16; ++it) {
        int u = it * 512 + tid;
        int mtl = u >> 9, kt = (u >> 5) & 15, ln = u & 31;
        int r = mtl * 16 + (ln >> 2), c = kt * 16 + (ln & 3) * 2;
        const float* p = x + ((size_t)t0 + r) * D_DIM + c;
        float2 v00 = __ldg((const float2*)p);
        float2 v80 = __ldg((const float2*)(p + 8 * D_DIM));
        float2 v08 = __ldg((const float2*)(p + 8));
        float2 v88 = __ldg((const float2*)(p + 8 * D_DIM + 8));
        uint4 q;
        q.x = h2pack(v00.x, v00.y);
        q.y = h2pack(v80.x, v80.y);
        q.z = h2pack(v08.x, v08.y);
        q.w = h2pack(v88.x, v88.y);
        *(uint4*)(sm + A_OFF + (uint32_t)((mtl * 16 + kt) * 32 + ln) * 16) = q;
    }

    float acc[4][4][4];
#pragma unroll
    for (int mt = 0; mt < 4; ++mt)
#pragma unroll
        for (int nt = 0; nt < 4; ++nt)
#pragma unroll
            for (int c = 0; c < 4; ++c) acc[mt][nt][c] = 0.f;

    uint32_t k1[8], k2[8];
#pragma unroll
    for (int s = 0; s < 8; ++s) { k1[s] = 0u; k2[s] = 0u; }

    const float* cesm = (const float*)(sm + ESQ_OFF);

    // 32 chunks; each = 2 groups of 2 stages with static slots.
    for (int GG = 0; GG < 32; ++GG) {
        // Group A: compute slots 0/1 (ktiles 0-7); prefetch into 2/3.
        CP_WAIT(0);
        __syncthreads();
        prefetch_stage(sb, tid, 4 * GG + 2, 32768);
        prefetch_stage(sb, tid, 4 * GG + 3, 49152);
        two_stages<0, 0>(sm, warpM, warpN, lane, acc);

        // Group B: compute slots 2/3 (ktiles 8-15); prefetch into 0/1.
        CP_WAIT(0);
        __syncthreads();
        if (GG < 31) {
            prefetch_stage(sb, tid, 4 * GG + 4, 0);
            prefetch_stage(sb, tid, 4 * GG + 5, 16384);
        }
        two_stages<2, 8>(sm, warpM, warpN, lane, acc);

        // Epilogue: chunk GG complete. w2 = (2*dot + 16 - esq)*2^27 > 0.
        {
            int n0 = GG * 128 + warpN * 32 + (lane & 3) * 2;
            uint32_t binv = 4095u - (uint32_t)n0;
            float2 cz[4];
#pragma unroll
            for (int nt = 0; nt < 4; ++nt)
                cz[nt] = *(const float2*)(cesm + n0 + nt * 8);
#pragma unroll
            for (int mt = 0; mt < 4; ++mt)
#pragma unroll
                for (int nt = 0; nt < 4; ++nt)
#pragma unroll
                    for (int c = 0; c < 4; ++c) {
                        float cesc = (c & 1) ? cz[nt].y : cz[nt].x;
                        float w2 = fmaf(2.0f * KBIG, acc[mt][nt][c], cesc);
                        acc[mt][nt][c] = 0.f;
                        uint32_t q2 = __float2uint_rz(w2);
                        uint32_t key = (q2 & 0xFFFFF000u) |
                                       (binv - (uint32_t)(nt * 8 + (c & 1)));
                        const int s = mt * 2 + (c >> 1);
                        uint32_t km = umin(k1[s], key);
                        k1[s] = umax(k1[s], key);
                        k2[s] = umax(k2[s], km);
                    }
        }
    }

    // ---- Tail: keys -> SMEM (dead ring slots 0/1) + g_ckey (for rescue) ----
    __syncthreads();
    uint32_t* skeys = (uint32_t*)(sm + B_OFF);
#pragma unroll
    for (int s = 0; s < 8; ++s) {
        int mt = s >> 1, ch = s & 1;
        int row = warpM * 64 + mt * 16 + ch * 8 + (lane >> 2);
        int slot = (warpN * 4 + (lane & 3)) * 2;
        uint2 kk2 = make_uint2(k1[s], k2[s]);
        *(uint2*)(skeys + row * 32 + slot) = kk2;
        *(uint2*)(g_ckey + ((size_t)t0 + row) * 32 + slot) = kk2;
    }
    __syncthreads();

    // ---- Confident-token merge + gather (warp per token, 16 tokens/warp) ----
    for (int it = 0; it < 16; ++it) {
        const int t = wid * 16 + it;
        const int tg = t0 + t;
        uint32_t key = skeys[t * 32 + lane];

        uint32_t kb = key;
#pragma unroll
        for (int off = 16; off > 0; off >>= 1)
            kb = umax(kb, __shfl_xor_sync(0xffffffffu, kb, off));
        uint32_t ex = (key == kb) ? 0u : key;
#pragma unroll
        for (int off = 16; off > 0; off >>= 1)
            ex = umax(ex, __shfl_xor_sync(0xffffffffu, ex, off));

        float v1 = (float)(kb >> 12) * (1.0f / KSCALE);
        float v2 = (float)(ex >> 12) * (1.0f / KSCALE);

        if (v1 - v2 >= EPS_GAP) {
            int best = 4095 - (int)(kb & 0xFFFu);
            const float4* src = (const float4*)(embed + (size_t)best * D_DIM);
            float4* dst = (float4*)(out_q + (size_t)tg * D_DIM);
            dst[lane] = src[lane];
            dst[lane + 32] = src[lane + 32];
            if (lane == 0 && out_i) out_i[tg] = (float)best;
        }
    }
}

// ---------------------------------------------------------------------------
// Rescue: recheck gap; early-exit for confident tokens (already written);
// exact fp32 rescore + gather for the rare ambiguous ones.
__global__ __launch_bounds__(256) void rescue_kernel(const float* __restrict__ x,
                                                     const float* __restrict__ embed,
                                                     float* __restrict__ out_q,
                                                     float* __restrict__ out_i) {
    const int lane = threadIdx.x & 31, wid = threadIdx.x >> 5;
    const int t = blockIdx.x * 8 + wid;

    uint32_t key = g_ckey[(size_t)t * 32 + lane];

    uint32_t kb = key;
#pragma unroll
    for (int off = 16; off > 0; off >>= 1)
        kb = umax(kb, __shfl_xor_sync(0xffffffffu, kb, off));
    uint32_t ex = (key == kb) ? 0u : key;
#pragma unroll
    for (int off = 16; off > 0; off >>= 1)
        ex = umax(ex, __shfl_xor_sync(0xffffffffu, ex, off));

    float v1 = (float)(kb >> 12) * (1.0f / KSCALE);
    float v2 = (float)(ex >> 12) * (1.0f / KSCALE);
    if (v1 - v2 >= EPS_GAP) return;   // warp-uniform: main already wrote it

    const float* xr = x + (size_t)t * D_DIM;
    float xv[8];
#pragma unroll
    for (int j = 0; j < 8; ++j) xv[j] = xr[lane + 32 * j];

    float p = 0.f;
#pragma unroll
    for (int j = 0; j < 8; ++j)
        p = __fadd_rn(p, __fmul_rn(xv[j], xv[j]));
#pragma unroll
    for (int off = 16; off > 0; off >>= 1)
        p = __fadd_rn(p, __shfl_xor_sync(0xffffffffu, p, off));
    const float xsq = p;

    int cand = 4095 - (int)(key & 0xFFFu);
    float bv = -FLT_MAX; int bi = 0x7fffffff;
    for (int c = 0; c < 32; ++c) {
        int idc = __shfl_sync(0xffffffffu, cand, c);
        const float* er = embed + (size_t)idc * D_DIM;
        float d = 0.f;
#pragma unroll
        for (int j = 0; j < 8; ++j)
            d = fmaf(xv[j], er[lane + 32 * j], d);
#pragma unroll
        for (int off = 16; off > 0; off >>= 1)
            d += __shfl_xor_sync(0xffffffffu, d, off);
        float t2v = __fsub_rn(xsq, __fmul_rn(2.f, d));
        float dn = -__fadd_rn(t2v, g_esq[idc]);
        if (dn > bv || (dn == bv && idc < bi)) { bv = dn; bi = idc; }
    }

    const float4* src = (const float4*)(embed + (size_t)bi * D_DIM);
    float4* dst = (float4*)(out_q + (size_t)t * D_DIM);
    dst[lane] = src[lane];
    dst[lane + 32] = src[lane + 32];
    if (lane == 0 && out_i) out_i[t] = (float)bi;
}

// ---------------------------------------------------------------------------
extern "C" void kernel_launch(void* const* d_in, const int* in_sizes, int n_in,
                              void* d_out, int out_size) {
    const float* x     = (const float*)d_in[0];
    const float* embed = (const float*)d_in[1];

    int T = in_sizes[2];  // 32768

    float* outq = (float*)d_out;
    float* outi = nullptr;
    if ((long long)out_size >= (long long)T * D_DIM + T)
        outi = outq + (size_t)T * D_DIM;

    prep_kernel<<<(128 * 1024) / 256, 256>>>(embed);

    cudaFuncSetAttribute(vq_mma_kernel,
                         cudaFuncAttributeMaxDynamicSharedMemorySize, SMEM_BYTES);
    vq_mma_kernel<<<T / 256, 512, SMEM_BYTES>>>(x, embed, outq, outi);

    rescue_kernel<<<T / 8, 256>>>(x, embed, outq, outi);
}

// round 15
// speedup vs baseline: 1.0160x; 1.0160x over previous
#include <cuda_runtime.h>
#include <cuda_fp16.h>
#include <cstdint>
#include <cfloat>

// Shapes fixed by dataset: T=32768 tokens, K=4096 codes, D=256.
#define T_TOK 32768
#define K_COD 4096
#define D_DIM 256
#define EPS_GAP 0.004f
#define KSCALE 32768.0f          // key resolution = 1/KSCALE
#define KBIG   134217728.0f      // KSCALE * 4096 = 2^27

// Main kernel: CTA = 256 tokens x full K, 512 threads, 16 warps = 4(M) x 4(N),
// warp tile 64 tok x 32 codes. N chunk 128 codes, k-stage 64 (4 HMMA k16),
// 128 stages as 64 groups of 2 (one barrier + one commit group per group).
#define A_OFF   0        // A frags fp16: [mtile16][ktile16][lane] uint4 = 128KB
#define B_OFF   131072   // ring: 4 stages x 16KB; slots 0/1 reused for keys
#define ESQ_OFF 196608   // cesc = (16 - esq)*2^27, 16KB
#define SMEM_BYTES 212992

__device__ uint4  g_bt[(size_t)128 * 1024];   // 2MB packed B fragments
__device__ float  g_esq[K_COD];               // ||e||^2 (for exact rescore)
__device__ float  g_cesc[K_COD];              // (16 - ||e||^2) * 2^27
__device__ uint32_t g_ckey[(size_t)T_TOK * 32];  // 4MB candidate keys

static __device__ __forceinline__ uint32_t smem_u32(const void* p) {
    uint32_t a;
    asm("{ .reg .u64 t; cvta.to.shared.u64 t, %1; cvt.u32.u64 %0, t; }"
        : "=r"(a) : "l"(p));
    return a;
}
static __device__ __forceinline__ void cp16(uint32_t dst, const void* src) {
    asm volatile("cp.async.cg.shared.global [%0], [%1], 16;"
                 :: "r"(dst), "l"(__cvta_generic_to_global(src)) : "memory");
}
#define CP_COMMIT() asm volatile("cp.async.commit_group;" ::: "memory")
#define CP_WAIT(n)  asm volatile("cp.async.wait_group %0;" :: "n"(n) : "memory")

static __device__ __forceinline__ void mma16(float& d0, float& d1, float& d2, float& d3,
                                             uint4 a, uint32_t b0, uint32_t b1) {
    asm volatile(
        "mma.sync.aligned.m16n8k16.row.col.f32.f16.f16.f32 "
        "{%0,%1,%2,%3}, {%4,%5,%6,%7}, {%8,%9}, {%0,%1,%2,%3};"
        : "+f"(d0), "+f"(d1), "+f"(d2), "+f"(d3)
        : "r"(a.x), "r"(a.y), "r"(a.z), "r"(a.w), "r"(b0), "r"(b1));
}
static __device__ __forceinline__ uint32_t h2pack(float a, float b) {
    __half2 h = __floats2half2_rn(a, b);
    return *(uint32_t*)&h;
}

// ---------------------------------------------------------------------------
// Fused prep: pack embed -> fp16 B fragments AND per-row esq/cesc.
__global__ void prep_kernel(const float* __restrict__ embed) {
    const int tid = threadIdx.x, lane = tid & 31, wrp = tid >> 5;

    {   // pack_b: u = [stage(128)][kk(4)][np(8)][lane(32)]
        uint32_t u = blockIdx.x * 256 + tid;
        int s = u >> 10, r = u & 1023;
        int kk = r >> 8, np = (r >> 5) & 7, ln = r & 31;
        int nc = s >> 2, q4 = s & 3;
        int k = q4 * 64 + kk * 16 + (ln & 3) * 2;
        int n0 = nc * 128 + np * 16 + (ln >> 2);
        const float* e0 = embed + (size_t)n0 * D_DIM + k;
        const float* e1 = e0 + 8 * D_DIM;
        uint4 q;
        q.x = h2pack(e0[0], e0[1]);
        q.y = h2pack(e0[8], e0[9]);
        q.z = h2pack(e1[0], e1[1]);
        q.w = h2pack(e1[8], e1[9]);
        g_bt[u] = q;
    }

    {   // esq: warp per code row, coalesced, deterministic shfl tree
        const int k = blockIdx.x * 8 + wrp;
        const float* row = embed + (size_t)k * D_DIM;
        float s = 0.f;
#pragma unroll
        for (int j = 0; j < 8; ++j) {
            float v = row[lane + 32 * j];
            s = __fadd_rn(s, __fmul_rn(v, v));
        }
#pragma unroll
        for (int off = 16; off > 0; off >>= 1)
            s = __fadd_rn(s, __shfl_xor_sync(0xffffffffu, s, off));
        if (lane == 0) {
            g_esq[k] = s;
            g_cesc[k] = (16.0f - s) * KBIG;
        }
    }
}

// ---------------------------------------------------------------------------
// Main: A-pack prologue + fp16 GEMM (2 stages/barrier) + key top-2 +
// confident-token gather tail.  (R13 structure; single commit per pair.)
__global__ __launch_bounds__(512, 1) void vq_mma_kernel(const float* __restrict__ x,
                                                        const float* __restrict__ embed,
                                                        float* __restrict__ out_q,
                                                        float* __restrict__ out_i) {
    extern __shared__ char sm[];
    const uint32_t sb = smem_u32(sm);
    const int tid = threadIdx.x, lane = tid & 31, wid = tid >> 5;
    const int warpM = wid & 3, warpN = wid >> 2;   // 4 x 4
    const int cta = blockIdx.x;
    const int t0 = cta * 256;

    // ---- Prologue: cesc + B stages 0,1 (one async group), then A convert ----
    {
        const uint4* es = (const uint4*)g_cesc;
#pragma unroll
        for (int i = 0; i < 2; ++i)
            cp16(sb + ESQ_OFF + (uint32_t)(i * 512 + tid) * 16, es + i * 512 + tid);
#pragma unroll
        for (int i = 0; i < 4; ++i)
            cp16(sb + B_OFF + (uint32_t)(i * 512 + tid) * 16, g_bt + i * 512 + tid);
        CP_COMMIT();
    }

    // A: fp16 fragments straight from global x.
#pragma unroll
    for (int it = 0; it < 16; ++it) {
        int u = it * 512 + tid;
        int mtl = u >> 9, kt = (u >> 5) & 15, ln = u & 31;
        int r = mtl * 16 + (ln >> 2), c = kt * 16 + (ln & 3) * 2;
        const float* p = x + ((size_t)t0 + r) * D_DIM + c;
        float2 v00 = __ldg((const float2*)p);
        float2 v80 = __ldg((const float2*)(p + 8 * D_DIM));
        float2 v08 = __ldg((const float2*)(p + 8));
        float2 v88 = __ldg((const float2*)(p + 8 * D_DIM + 8));
        uint4 q;
        q.x = h2pack(v00.x, v00.y);
        q.y = h2pack(v80.x, v80.y);
        q.z = h2pack(v08.x, v08.y);
        q.w = h2pack(v88.x, v88.y);
        *(uint4*)(sm + A_OFF + (uint32_t)((mtl * 16 + kt) * 32 + ln) * 16) = q;
    }

    float acc[4][4][4];
#pragma unroll
    for (int mt = 0; mt < 4; ++mt)
#pragma unroll
        for (int nt = 0; nt < 4; ++nt)
#pragma unroll
            for (int c = 0; c < 4; ++c) acc[mt][nt][c] = 0.f;

    uint32_t k1[8], k2[8];
#pragma unroll
    for (int s = 0; s < 8; ++s) { k1[s] = 0u; k2[s] = 0u; }

    const float* cesm = (const float*)(sm + ESQ_OFF);
    const int eb = warpN * 32 + (lane & 3) * 2;   // GG-invariant epilogue base

    // 64 groups x 2 stages; one wait+barrier+commit per group.
    for (int G = 0; G < 64; ++G) {
        const int g0 = 2 * G;
        CP_WAIT(0);
        __syncthreads();
        if (g0 + 2 < 128) {
            const uint4* bs = g_bt + (size_t)(g0 + 2) * 1024;
            uint32_t bd = sb + B_OFF + (uint32_t)((g0 + 2) & 3) * 16384;
#pragma unroll
            for (int i = 0; i < 2; ++i)
                cp16(bd + (uint32_t)(i * 512 + tid) * 16, bs + i * 512 + tid);
            const uint4* bs2 = g_bt + (size_t)(g0 + 3) * 1024;
            uint32_t bd2 = sb + B_OFF + (uint32_t)((g0 + 3) & 3) * 16384;
#pragma unroll
            for (int i = 0; i < 2; ++i)
                cp16(bd2 + (uint32_t)(i * 512 + tid) * 16, bs2 + i * 512 + tid);
            CP_COMMIT();
        }

#pragma unroll
        for (int hs = 0; hs < 2; ++hs) {
            const int g = g0 + hs;
            const char* bbuf = sm + B_OFF + (g & 3) * 16384;
#pragma unroll
            for (int kk = 0; kk < 4; ++kk) {
                int ktile = (g & 3) * 4 + kk;
                uint4 a[4];
#pragma unroll
                for (int mt = 0; mt < 4; ++mt)
                    a[mt] = *(const uint4*)(sm + A_OFF +
                            (size_t)(((warpM * 4 + mt) * 16 + ktile) * 32 + lane) * 16);
#pragma unroll
                for (int npl = 0; npl < 2; ++npl) {
                    uint4 bq = *(const uint4*)(bbuf +
                               (size_t)((kk * 8 + warpN * 2 + npl) * 32 + lane) * 16);
                    int ne = 2 * npl, no = 2 * npl + 1;
#pragma unroll
                    for (int mt = 0; mt < 4; ++mt) {
                        mma16(acc[mt][ne][0], acc[mt][ne][1], acc[mt][ne][2], acc[mt][ne][3],
                              a[mt], bq.x, bq.y);
                        mma16(acc[mt][no][0], acc[mt][no][1], acc[mt][no][2], acc[mt][no][3],
                              a[mt], bq.z, bq.w);
                    }
                }
            }
        }

        if (G & 1) {
            int n0 = (G >> 1) * 128 + eb;
            uint32_t binv = 4095u - (uint32_t)n0;
            float2 cz[4];
#pragma unroll
            for (int nt = 0; nt < 4; ++nt)
                cz[nt] = *(const float2*)(cesm + n0 + nt * 8);
#pragma unroll
            for (int mt = 0; mt < 4; ++mt)
#pragma unroll
                for (int nt = 0; nt < 4; ++nt)
#pragma unroll
                    for (int c = 0; c < 4; ++c) {
                        float cesc = (c & 1) ? cz[nt].y : cz[nt].x;
                        float w2 = fmaf(2.0f * KBIG, acc[mt][nt][c], cesc);
                        acc[mt][nt][c] = 0.f;
                        uint32_t q2 = __float2uint_rz(w2);
                        uint32_t key = (q2 & 0xFFFFF000u) |
                                       (binv - (uint32_t)(nt * 8 + (c & 1)));
                        const int s = mt * 2 + (c >> 1);
                        uint32_t km = umin(k1[s], key);
                        k1[s] = umax(k1[s], key);
                        k2[s] = umax(k2[s], km);
                    }
        }
    }

    // ---- Tail: keys -> SMEM (dead ring slots 0/1) + g_ckey (for rescue) ----
    __syncthreads();
    uint32_t* skeys = (uint32_t*)(sm + B_OFF);
#pragma unroll
    for (int s = 0; s < 8; ++s) {
        int mt = s >> 1, ch = s & 1;
        int row = warpM * 64 + mt * 16 + ch * 8 + (lane >> 2);
        int slot = (warpN * 4 + (lane & 3)) * 2;
        uint2 kk2 = make_uint2(k1[s], k2[s]);
        *(uint2*)(skeys + row * 32 + slot) = kk2;
        *(uint2*)(g_ckey + ((size_t)t0 + row) * 32 + slot) = kk2;
    }
    __syncthreads();

    // ---- Confident-token merge + gather (warp per token, 16 tokens/warp) ----
    for (int it = 0; it < 16; ++it) {
        const int t = wid * 16 + it;
        const int tg = t0 + t;
        uint32_t key = skeys[t * 32 + lane];

        uint32_t kb = key;
#pragma unroll
        for (int off = 16; off > 0; off >>= 1)
            kb = umax(kb, __shfl_xor_sync(0xffffffffu, kb, off));
        uint32_t ex = (key == kb) ? 0u : key;
#pragma unroll
        for (int off = 16; off > 0; off >>= 1)
            ex = umax(ex, __shfl_xor_sync(0xffffffffu, ex, off));

        float v1 = (float)(kb >> 12) * (1.0f / KSCALE);
        float v2 = (float)(ex >> 12) * (1.0f / KSCALE);

        if (v1 - v2 >= EPS_GAP) {
            int best = 4095 - (int)(kb & 0xFFFu);
            const float4* src = (const float4*)(embed + (size_t)best * D_DIM);
            float4* dst = (float4*)(out_q + (size_t)tg * D_DIM);
            dst[lane] = src[lane];
            dst[lane + 32] = src[lane + 32];
            if (lane == 0 && out_i) out_i[tg] = (float)best;
        }
    }
}

// ---------------------------------------------------------------------------
// Rescue: recheck gap; early-exit for confident tokens (already written);
// exact fp32 rescore + gather for the rare ambiguous ones.
__global__ __launch_bounds__(256) void rescue_kernel(const float* __restrict__ x,
                                                     const float* __restrict__ embed,
                                                     float* __restrict__ out_q,
                                                     float* __restrict__ out_i) {
    const int lane = threadIdx.x & 31, wid = threadIdx.x >> 5;
    const int t = blockIdx.x * 8 + wid;

    uint32_t key = g_ckey[(size_t)t * 32 + lane];

    uint32_t kb = key;
#pragma unroll
    for (int off = 16; off > 0; off >>= 1)
        kb = umax(kb, __shfl_xor_sync(0xffffffffu, kb, off));
    uint32_t ex = (key == kb) ? 0u : key;
#pragma unroll
    for (int off = 16; off > 0; off >>= 1)
        ex = umax(ex, __shfl_xor_sync(0xffffffffu, ex, off));

    float v1 = (float)(kb >> 12) * (1.0f / KSCALE);
    float v2 = (float)(ex >> 12) * (1.0f / KSCALE);
    if (v1 - v2 >= EPS_GAP) return;   // warp-uniform: main already wrote it

    const float* xr = x + (size_t)t * D_DIM;
    float xv[8];
#pragma unroll
    for (int j = 0; j < 8; ++j) xv[j] = xr[lane + 32 * j];

    float p = 0.f;
#pragma unroll
    for (int j = 0; j < 8; ++j)
        p = __fadd_rn(p, __fmul_rn(xv[j], xv[j]));
#pragma unroll
    for (int off = 16; off > 0; off >>= 1)
        p = __fadd_rn(p, __shfl_xor_sync(0xffffffffu, p, off));
    const float xsq = p;

    int cand = 4095 - (int)(key & 0xFFFu);
    float bv = -FLT_MAX; int bi = 0x7fffffff;
    for (int c = 0; c < 32; ++c) {
        int idc = __shfl_sync(0xffffffffu, cand, c);
        const float* er = embed + (size_t)idc * D_DIM;
        float d = 0.f;
#pragma unroll
        for (int j = 0; j < 8; ++j)
            d = fmaf(xv[j], er[lane + 32 * j], d);
#pragma unroll
        for (int off = 16; off > 0; off >>= 1)
            d += __shfl_xor_sync(0xffffffffu, d, off);
        float t2v = __fsub_rn(xsq, __fmul_rn(2.f, d));
        float dn = -__fadd_rn(t2v, g_esq[idc]);
        if (dn > bv || (dn == bv && idc < bi)) { bv = dn; bi = idc; }
    }

    const float4* src = (const float4*)(embed + (size_t)bi * D_DIM);
    float4* dst = (float4*)(out_q + (size_t)t * D_DIM);
    dst[lane] = src[lane];
    dst[lane + 32] = src[lane + 32];
    if (lane == 0 && out_i) out_i[t] = (float)bi;
}

// ---------------------------------------------------------------------------
extern "C" void kernel_launch(void* const* d_in, const int* in_sizes, int n_in,
                              void* d_out, int out_size) {
    const float* x     = (const float*)d_in[0];
    const float* embed = (const float*)d_in[1];

    int T = in_sizes[2];  // 32768

    float* outq = (float*)d_out;
    float* outi = nullptr;
    if ((long long)out_size >= (long long)T * D_DIM + T)
        outi = outq + (size_t)T * D_DIM;

    prep_kernel<<<(128 * 1024) / 256, 256>>>(embed);

    cudaFuncSetAttribute(vq_mma_kernel,
                         cudaFuncAttributeMaxDynamicSharedMemorySize, SMEM_BYTES);
    vq_mma_kernel<<<T / 256, 512, SMEM_BYTES>>>(x, embed, outq, outi);

    rescue_kernel<<<T / 8, 256>>>(x, embed, outq, outi);
}

// round 16
// speedup vs baseline: 1.0252x; 1.0090x over previous
#include <cuda_runtime.h>
#include <cuda_fp16.h>
#include <cstdint>
#include <cfloat>

// Shapes fixed by dataset: T=32768 tokens, K=4096 codes, D=256.
#define T_TOK 32768
#define K_COD 4096
#define D_DIM 256
#define EPS_GAP 0.004f
#define KSCALE 32768.0f          // key resolution = 1/KSCALE
#define KBIG   134217728.0f      // KSCALE * 4096 = 2^27

// Main kernel: CTA = 256 tokens x full K, 256 threads, 8 warps = 4(M) x 2(N),
// warp tile 64 tok x 64 codes. N chunk 128 codes, k-stage 64 (4 HMMA k16),
// 128 stages as 64 groups of 2; software-pipelined fragment loads.
#define A_OFF   0        // A frags fp16: [mtile16][ktile16][lane] uint4 = 128KB
#define B_OFF   131072   // ring: 4 stages x 16KB; slot 0 reused for keys
#define ESQ_OFF 196608   // cesc = (16 - esq)*2^27, 16KB
#define SMEM_BYTES 212992

__device__ uint4  g_bt[(size_t)128 * 1024];   // 2MB packed B fragments
__device__ float  g_esq[K_COD];               // ||e||^2 (for exact rescore)
__device__ float  g_cesc[K_COD];              // (16 - ||e||^2) * 2^27
__device__ uint32_t g_ckey[(size_t)T_TOK * 16];  // 2MB candidate keys

static __device__ __forceinline__ uint32_t smem_u32(const void* p) {
    uint32_t a;
    asm("{ .reg .u64 t; cvta.to.shared.u64 t, %1; cvt.u32.u64 %0, t; }"
        : "=r"(a) : "l"(p));
    return a;
}
static __device__ __forceinline__ void cp16(uint32_t dst, const void* src) {
    asm volatile("cp.async.cg.shared.global [%0], [%1], 16;"
                 :: "r"(dst), "l"(__cvta_generic_to_global(src)) : "memory");
}
#define CP_COMMIT() asm volatile("cp.async.commit_group;" ::: "memory")
#define CP_WAIT(n)  asm volatile("cp.async.wait_group %0;" :: "n"(n) : "memory")

static __device__ __forceinline__ void mma16(float& d0, float& d1, float& d2, float& d3,
                                             uint4 a, uint32_t b0, uint32_t b1) {
    asm volatile(
        "mma.sync.aligned.m16n8k16.row.col.f32.f16.f16.f32 "
        "{%0,%1,%2,%3}, {%4,%5,%6,%7}, {%8,%9}, {%0,%1,%2,%3};"
        : "+f"(d0), "+f"(d1), "+f"(d2), "+f"(d3)
        : "r"(a.x), "r"(a.y), "r"(a.z), "r"(a.w), "r"(b0), "r"(b1));
}
static __device__ __forceinline__ uint32_t h2pack(float a, float b) {
    __half2 h = __floats2half2_rn(a, b);
    return *(uint32_t*)&h;
}

// ---------------------------------------------------------------------------
// Fused prep: pack embed -> fp16 B fragments AND per-row esq/cesc. (unchanged)
__global__ void prep_kernel(const float* __restrict__ embed) {
    const int tid = threadIdx.x, lane = tid & 31, wrp = tid >> 5;

    {   // pack_b: u = [stage(128)][kk(4)][np(8)][lane(32)]
        uint32_t u = blockIdx.x * 256 + tid;
        int s = u >> 10, r = u & 1023;
        int kk = r >> 8, np = (r >> 5) & 7, ln = r & 31;
        int nc = s >> 2, q4 = s & 3;
        int k = q4 * 64 + kk * 16 + (ln & 3) * 2;
        int n0 = nc * 128 + np * 16 + (ln >> 2);
        const float* e0 = embed + (size_t)n0 * D_DIM + k;
        const float* e1 = e0 + 8 * D_DIM;
        uint4 q;
        q.x = h2pack(e0[0], e0[1]);
        q.y = h2pack(e0[8], e0[9]);
        q.z = h2pack(e1[0], e1[1]);
        q.w = h2pack(e1[8], e1[9]);
        g_bt[u] = q;
    }

    {   // esq: warp per code row
        const int k = blockIdx.x * 8 + wrp;
        const float* row = embed + (size_t)k * D_DIM;
        float s = 0.f;
#pragma unroll
        for (int j = 0; j < 8; ++j) {
            float v = row[lane + 32 * j];
            s = __fadd_rn(s, __fmul_rn(v, v));
        }
#pragma unroll
        for (int off = 16; off > 0; off >>= 1)
            s = __fadd_rn(s, __shfl_xor_sync(0xffffffffu, s, off));
        if (lane == 0) {
            g_esq[k] = s;
            g_cesc[k] = (16.0f - s) * KBIG;
        }
    }
}

// ---------------------------------------------------------------------------
// One group = 2 k-stages = 8 kk-steps, software-pipelined fragment loads.
template<int SLOT0, int KT0>
static __device__ __forceinline__ void group_mma(
    const char* sm, int warpM, int warpN, int lane, float (&acc)[4][8][4]) {
    uint4 a_cur[4], b_cur[4];
    // load flat step 0
    {
        const char* bbuf = sm + B_OFF + SLOT0 * 16384;
#pragma unroll
        for (int mt = 0; mt < 4; ++mt)
            a_cur[mt] = *(const uint4*)(sm + A_OFF +
                    (size_t)(((warpM * 4 + mt) * 16 + KT0) * 32 + lane) * 16);
#pragma unroll
        for (int npl = 0; npl < 4; ++npl)
            b_cur[npl] = *(const uint4*)(bbuf +
                    (size_t)((warpN * 4 + npl) * 32 + lane) * 16);
    }
#pragma unroll
    for (int f = 0; f < 8; ++f) {
        uint4 a_nxt[4], b_nxt[4];
        if (f < 7) {
            const int fn = f + 1;
            const int ktile = KT0 + fn;
            const char* bbuf = sm + B_OFF + (SLOT0 + (fn >> 2)) * 16384;
#pragma unroll
            for (int mt = 0; mt < 4; ++mt)
                a_nxt[mt] = *(const uint4*)(sm + A_OFF +
                        (size_t)(((warpM * 4 + mt) * 16 + ktile) * 32 + lane) * 16);
#pragma unroll
            for (int npl = 0; npl < 4; ++npl)
                b_nxt[npl] = *(const uint4*)(bbuf +
                        (size_t)(((fn & 3) * 8 + warpN * 4 + npl) * 32 + lane) * 16);
        }
#pragma unroll
        for (int npl = 0; npl < 4; ++npl) {
            const int ne = 2 * npl, no = 2 * npl + 1;
#pragma unroll
            for (int mt = 0; mt < 4; ++mt) {
                mma16(acc[mt][ne][0], acc[mt][ne][1], acc[mt][ne][2], acc[mt][ne][3],
                      a_cur[mt], b_cur[npl].x, b_cur[npl].y);
                mma16(acc[mt][no][0], acc[mt][no][1], acc[mt][no][2], acc[mt][no][3],
                      a_cur[mt], b_cur[npl].z, b_cur[npl].w);
            }
        }
        if (f < 7) {
#pragma unroll
            for (int mt = 0; mt < 4; ++mt) a_cur[mt] = a_nxt[mt];
#pragma unroll
            for (int npl = 0; npl < 4; ++npl) b_cur[npl] = b_nxt[npl];
        }
    }
}

// Prefetch one 16KB B stage (4 cp16/thread at 256 threads).
static __device__ __forceinline__ void prefetch_stage(uint32_t sb, int tid, int g,
                                                      uint32_t slotoff) {
    const uint4* bs = g_bt + (size_t)g * 1024;
#pragma unroll
    for (int i = 0; i < 4; ++i)
        cp16(sb + B_OFF + slotoff + (uint32_t)(i * 256 + tid) * 16, bs + i * 256 + tid);
}

// ---------------------------------------------------------------------------
// Main: A-pack prologue + pipelined fp16 GEMM + int-key top-2 +
// confident-token gather tail. 256 threads, 8 warps 4(M) x 2(N).
__global__ __launch_bounds__(256, 1) void vq_mma_kernel(const float* __restrict__ x,
                                                        const float* __restrict__ embed,
                                                        float* __restrict__ out_q,
                                                        float* __restrict__ out_i) {
    extern __shared__ char sm[];
    const uint32_t sb = smem_u32(sm);
    const int tid = threadIdx.x, lane = tid & 31, wid = tid >> 5;
    const int warpM = wid & 3, warpN = wid >> 2;   // 4 x 2
    const int cta = blockIdx.x;
    const int t0 = cta * 256;

    // ---- Prologue: cesc + B stages 0,1 (one async group) ----
    {
        const uint4* es = (const uint4*)g_cesc;
#pragma unroll
        for (int i = 0; i < 4; ++i)
            cp16(sb + ESQ_OFF + (uint32_t)(i * 256 + tid) * 16, es + i * 256 + tid);
        prefetch_stage(sb, tid, 0, 0);
        prefetch_stage(sb, tid, 1, 16384);
        CP_COMMIT();
    }

    // A: fp16 fragments straight from global x (32 units/thread).
#pragma unroll
    for (int it = 0; it < 32; ++it) {
        int u = it * 256 + tid;
        int mtl = u >> 9, kt = (u >> 5) & 15, ln = u & 31;
        int r = mtl * 16 + (ln >> 2), c = kt * 16 + (ln & 3) * 2;
        const float* p = x + ((size_t)t0 + r) * D_DIM + c;
        float2 v00 = __ldg((const float2*)p);
        float2 v80 = __ldg((const float2*)(p + 8 * D_DIM));
        float2 v08 = __ldg((const float2*)(p + 8));
        float2 v88 = __ldg((const float2*)(p + 8 * D_DIM + 8));
        uint4 q;
        q.x = h2pack(v00.x, v00.y);
        q.y = h2pack(v80.x, v80.y);
        q.z = h2pack(v08.x, v08.y);
        q.w = h2pack(v88.x, v88.y);
        *(uint4*)(sm + A_OFF + (uint32_t)((mtl * 16 + kt) * 32 + ln) * 16) = q;
    }

    float acc[4][8][4];
#pragma unroll
    for (int mt = 0; mt < 4; ++mt)
#pragma unroll
        for (int nt = 0; nt < 8; ++nt)
#pragma unroll
            for (int c = 0; c < 4; ++c) acc[mt][nt][c] = 0.f;

    uint32_t k1[8], k2[8];
#pragma unroll
    for (int s = 0; s < 8; ++s) { k1[s] = 0u; k2[s] = 0u; }

    const float* cesm = (const float*)(sm + ESQ_OFF);
    const int eb = warpN * 64 + (lane & 3) * 2;   // chunk-invariant epilogue base

    for (int GG = 0; GG < 32; ++GG) {
        // Group A: compute slots 0/1 (ktiles 0-7); prefetch into 2/3.
        CP_WAIT(0);
        __syncthreads();
        prefetch_stage(sb, tid, 4 * GG + 2, 32768);
        prefetch_stage(sb, tid, 4 * GG + 3, 49152);
        CP_COMMIT();
        group_mma<0, 0>(sm, warpM, warpN, lane, acc);

        // Group B: compute slots 2/3 (ktiles 8-15); prefetch into 0/1.
        CP_WAIT(0);
        __syncthreads();
        if (GG < 31) {
            prefetch_stage(sb, tid, 4 * GG + 4, 0);
            prefetch_stage(sb, tid, 4 * GG + 5, 16384);
            CP_COMMIT();
        }
        group_mma<2, 8>(sm, warpM, warpN, lane, acc);

        // Epilogue: chunk GG complete. w2 = (2*dot + 16 - esq)*2^27 > 0.
        {
            int n0 = GG * 128 + eb;
            uint32_t binv = 4095u - (uint32_t)n0;
            float2 cz[8];
#pragma unroll
            for (int nt = 0; nt < 8; ++nt)
                cz[nt] = *(const float2*)(cesm + n0 + nt * 8);
#pragma unroll
            for (int mt = 0; mt < 4; ++mt)
#pragma unroll
                for (int nt = 0; nt < 8; ++nt)
#pragma unroll
                    for (int c = 0; c < 4; ++c) {
                        float cesc = (c & 1) ? cz[nt].y : cz[nt].x;
                        float w2 = fmaf(2.0f * KBIG, acc[mt][nt][c], cesc);
                        acc[mt][nt][c] = 0.f;
                        uint32_t q2 = __float2uint_rz(w2);
                        uint32_t key = (q2 & 0xFFFFF000u) |
                                       (binv - (uint32_t)(nt * 8 + (c & 1)));
                        const int s = mt * 2 + (c >> 1);
                        uint32_t km = umin(k1[s], key);
                        k1[s] = umax(k1[s], key);
                        k2[s] = umax(k2[s], km);
                    }
        }
    }

    // ---- Tail: keys -> SMEM (dead ring slot 0) + g_ckey (for rescue) ----
    __syncthreads();
    uint32_t* skeys = (uint32_t*)(sm + B_OFF);   // 256 tokens x 16 keys = 16KB
#pragma unroll
    for (int s = 0; s < 8; ++s) {
        int mt = s >> 1, ch = s & 1;
        int row = warpM * 64 + mt * 16 + ch * 8 + (lane >> 2);
        int slot = (warpN * 4 + (lane & 3)) * 2;
        uint2 kk2 = make_uint2(k1[s], k2[s]);
        *(uint2*)(skeys + row * 16 + slot) = kk2;
        *(uint2*)(g_ckey + ((size_t)t0 + row) * 16 + slot) = kk2;
    }
    __syncthreads();

    // ---- Confident-token merge + gather (warp per token, 32 tokens/warp) ----
    for (int it = 0; it < 32; ++it) {
        const int t = wid * 32 + it;
        const int tg = t0 + t;
        uint32_t key = (lane < 16) ? skeys[t * 16 + lane] : 0u;

        uint32_t kb = key;
#pragma unroll
        for (int off = 16; off > 0; off >>= 1)
            kb = umax(kb, __shfl_xor_sync(0xffffffffu, kb, off));
        uint32_t ex = (key == kb) ? 0u : key;
#pragma unroll
        for (int off = 16; off > 0; off >>= 1)
            ex = umax(ex, __shfl_xor_sync(0xffffffffu, ex, off));

        float v1 = (float)(kb >> 12) * (1.0f / KSCALE);
        float v2 = (float)(ex >> 12) * (1.0f / KSCALE);

        if (v1 - v2 >= EPS_GAP) {
            int best = 4095 - (int)(kb & 0xFFFu);
            const float4* src = (const float4*)(embed + (size_t)best * D_DIM);
            float4* dst = (float4*)(out_q + (size_t)tg * D_DIM);
            dst[lane] = src[lane];
            dst[lane + 32] = src[lane + 32];
            if (lane == 0 && out_i) out_i[tg] = (float)best;
        }
    }
}

// ---------------------------------------------------------------------------
// Rescue: recheck gap; early-exit for confident tokens (already written);
// exact fp32 rescore + gather for the rare ambiguous ones (16 candidates).
__global__ __launch_bounds__(256) void rescue_kernel(const float* __restrict__ x,
                                                     const float* __restrict__ embed,
                                                     float* __restrict__ out_q,
                                                     float* __restrict__ out_i) {
    const int lane = threadIdx.x & 31, wid = threadIdx.x >> 5;
    const int t = blockIdx.x * 8 + wid;

    uint32_t key = (lane < 16) ? g_ckey[(size_t)t * 16 + lane] : 0u;

    uint32_t kb = key;
#pragma unroll
    for (int off = 16; off > 0; off >>= 1)
        kb = umax(kb, __shfl_xor_sync(0xffffffffu, kb, off));
    uint32_t ex = (key == kb) ? 0u : key;
#pragma unroll
    for (int off = 16; off > 0; off >>= 1)
        ex = umax(ex, __shfl_xor_sync(0xffffffffu, ex, off));

    float v1 = (float)(kb >> 12) * (1.0f / KSCALE);
    float v2 = (float)(ex >> 12) * (1.0f / KSCALE);
    if (v1 - v2 >= EPS_GAP) return;   // warp-uniform: main already wrote it

    const float* xr = x + (size_t)t * D_DIM;
    float xv[8];
#pragma unroll
    for (int j = 0; j < 8; ++j) xv[j] = xr[lane + 32 * j];

    float p = 0.f;
#pragma unroll
    for (int j = 0; j < 8; ++j)
        p = __fadd_rn(p, __fmul_rn(xv[j], xv[j]));
#pragma unroll
    for (int off = 16; off > 0; off >>= 1)
        p = __fadd_rn(p, __shfl_xor_sync(0xffffffffu, p, off));
    const float xsq = p;

    int cand = 4095 - (int)(key & 0xFFFu);
    float bv = -FLT_MAX; int bi = 0x7fffffff;
    for (int c = 0; c < 16; ++c) {
        int idc = __shfl_sync(0xffffffffu, cand, c);
        const float* er = embed + (size_t)idc * D_DIM;
        float d = 0.f;
#pragma unroll
        for (int j = 0; j < 8; ++j)
            d = fmaf(xv[j], er[lane + 32 * j], d);
#pragma unroll
        for (int off = 16; off > 0; off >>= 1)
            d += __shfl_xor_sync(0xffffffffu, d, off);
        float t2v = __fsub_rn(xsq, __fmul_rn(2.f, d));
        float dn = -__fadd_rn(t2v, g_esq[idc]);
        if (dn > bv || (dn == bv && idc < bi)) { bv = dn; bi = idc; }
    }

    const float4* src = (const float4*)(embed + (size_t)bi * D_DIM);
    float4* dst = (float4*)(out_q + (size_t)t * D_DIM);
    dst[lane] = src[lane];
    dst[lane + 32] = src[lane + 32];
    if (lane == 0 && out_i) out_i[t] = (float)bi;
}

// ---------------------------------------------------------------------------
extern "C" void kernel_launch(void* const* d_in, const int* in_sizes, int n_in,
                              void* d_out, int out_size) {
    const float* x     = (const float*)d_in[0];
    const float* embed = (const float*)d_in[1];

    int T = in_sizes[2];  // 32768

    float* outq = (float*)d_out;
    float* outi = nullptr;
    if ((long long)out_size >= (long long)T * D_DIM + T)
        outi = outq + (size_t)T * D_DIM;

    prep_kernel<<<(128 * 1024) / 256, 256>>>(embed);

    cudaFuncSetAttribute(vq_mma_kernel,
                         cudaFuncAttributeMaxDynamicSharedMemorySize, SMEM_BYTES);
    vq_mma_kernel<<<T / 256, 256, SMEM_BYTES>>>(x, embed, outq, outi);

    rescue_kernel<<<T / 8, 256>>>(x, embed, outq, outi);
}

// round 17
// speedup vs baseline: 1.0862x; 1.0595x over previous
#include <cuda_runtime.h>
#include <cuda_fp16.h>
#include <cstdint>
#include <cfloat>

// Shapes fixed by dataset: T=32768 tokens, K=4096 codes, D=256.
#define T_TOK 32768
#define K_COD 4096
#define D_DIM 256
#define EPS_GAP 0.004f
#define KSCALE 32768.0f          // key resolution = 1/KSCALE
#define FMAGIC 8388608.0f        // 2^23 exponent-pinning bias

// Main kernel: CTA = 256 tokens x full K, 256 threads, 8 warps = 4(M) x 2(N),
// warp tile 64 tok x 64 codes. N chunk 128 codes, k-stage 64 (4 HMMA k16),
// 128 stages as 64 groups of 2; software-pipelined fragment loads.
#define A_OFF   0        // A frags fp16: [mtile16][ktile16][lane] uint4 = 128KB
#define B_OFF   131072   // ring: 4 stages x 16KB; slot 0 reused for keys
#define ESQ_OFF 196608   // cesc = (16 - esq)*KSCALE + 2^23, 16KB
#define SMEM_BYTES 212992

__device__ uint4  g_bt[(size_t)128 * 1024];   // 2MB packed B fragments
__device__ float  g_esq[K_COD];               // ||e||^2 (for exact rescore)
__device__ float  g_cesc[K_COD];              // (16 - ||e||^2)*KSCALE + 2^23
__device__ uint32_t g_ckey[(size_t)T_TOK * 16];  // 2MB candidate keys

static __device__ __forceinline__ uint32_t smem_u32(const void* p) {
    uint32_t a;
    asm("{ .reg .u64 t; cvta.to.shared.u64 t, %1; cvt.u32.u64 %0, t; }"
        : "=r"(a) : "l"(p));
    return a;
}
static __device__ __forceinline__ void cp16(uint32_t dst, const void* src) {
    asm volatile("cp.async.cg.shared.global [%0], [%1], 16;"
                 :: "r"(dst), "l"(__cvta_generic_to_global(src)) : "memory");
}
#define CP_COMMIT() asm volatile("cp.async.commit_group;" ::: "memory")
#define CP_WAIT(n)  asm volatile("cp.async.wait_group %0;" :: "n"(n) : "memory")

static __device__ __forceinline__ void mma16(float& d0, float& d1, float& d2, float& d3,
                                             uint4 a, uint32_t b0, uint32_t b1) {
    asm volatile(
        "mma.sync.aligned.m16n8k16.row.col.f32.f16.f16.f32 "
        "{%0,%1,%2,%3}, {%4,%5,%6,%7}, {%8,%9}, {%0,%1,%2,%3};"
        : "+f"(d0), "+f"(d1), "+f"(d2), "+f"(d3)
        : "r"(a.x), "r"(a.y), "r"(a.z), "r"(a.w), "r"(b0), "r"(b1));
}
static __device__ __forceinline__ uint32_t h2pack(float a, float b) {
    __half2 h = __floats2half2_rn(a, b);
    return *(uint32_t*)&h;
}

// ---------------------------------------------------------------------------
// Fused prep: pack embed -> fp16 B fragments AND per-row esq/cesc.
__global__ void prep_kernel(const float* __restrict__ embed) {
    const int tid = threadIdx.x, lane = tid & 31, wrp = tid >> 5;

    {   // pack_b: u = [stage(128)][kk(4)][np(8)][lane(32)]
        uint32_t u = blockIdx.x * 256 + tid;
        int s = u >> 10, r = u & 1023;
        int kk = r >> 8, np = (r >> 5) & 7, ln = r & 31;
        int nc = s >> 2, q4 = s & 3;
        int k = q4 * 64 + kk * 16 + (ln & 3) * 2;
        int n0 = nc * 128 + np * 16 + (ln >> 2);
        const float* e0 = embed + (size_t)n0 * D_DIM + k;
        const float* e1 = e0 + 8 * D_DIM;
        uint4 q;
        q.x = h2pack(e0[0], e0[1]);
        q.y = h2pack(e0[8], e0[9]);
        q.z = h2pack(e1[0], e1[1]);
        q.w = h2pack(e1[8], e1[9]);
        g_bt[u] = q;
    }

    {   // esq: warp per code row
        const int k = blockIdx.x * 8 + wrp;
        const float* row = embed + (size_t)k * D_DIM;
        float s = 0.f;
#pragma unroll
        for (int j = 0; j < 8; ++j) {
            float v = row[lane + 32 * j];
            s = __fadd_rn(s, __fmul_rn(v, v));
        }
#pragma unroll
        for (int off = 16; off > 0; off >>= 1)
            s = __fadd_rn(s, __shfl_xor_sync(0xffffffffu, s, off));
        if (lane == 0) {
            g_esq[k] = s;
            g_cesc[k] = (16.0f - s) * KSCALE + FMAGIC;
        }
    }
}

// ---------------------------------------------------------------------------
// One group = 2 k-stages = 8 kk-steps, software-pipelined fragment loads.
template<int SLOT0, int KT0>
static __device__ __forceinline__ void group_mma(
    const char* sm, int warpM, int warpN, int lane, float (&acc)[4][8][4]) {
    uint4 a_cur[4], b_cur[4];
    {
        const char* bbuf = sm + B_OFF + SLOT0 * 16384;
#pragma unroll
        for (int mt = 0; mt < 4; ++mt)
            a_cur[mt] = *(const uint4*)(sm + A_OFF +
                    (size_t)(((warpM * 4 + mt) * 16 + KT0) * 32 + lane) * 16);
#pragma unroll
        for (int npl = 0; npl < 4; ++npl)
            b_cur[npl] = *(const uint4*)(bbuf +
                    (size_t)((warpN * 4 + npl) * 32 + lane) * 16);
    }
#pragma unroll
    for (int f = 0; f < 8; ++f) {
        uint4 a_nxt[4], b_nxt[4];
        if (f < 7) {
            const int fn = f + 1;
            const int ktile = KT0 + fn;
            const char* bbuf = sm + B_OFF + (SLOT0 + (fn >> 2)) * 16384;
#pragma unroll
            for (int mt = 0; mt < 4; ++mt)
                a_nxt[mt] = *(const uint4*)(sm + A_OFF +
                        (size_t)(((warpM * 4 + mt) * 16 + ktile) * 32 + lane) * 16);
#pragma unroll
            for (int npl = 0; npl < 4; ++npl)
                b_nxt[npl] = *(const uint4*)(bbuf +
                        (size_t)(((fn & 3) * 8 + warpN * 4 + npl) * 32 + lane) * 16);
        }
#pragma unroll
        for (int npl = 0; npl < 4; ++npl) {
            const int ne = 2 * npl, no = 2 * npl + 1;
#pragma unroll
            for (int mt = 0; mt < 4; ++mt) {
                mma16(acc[mt][ne][0], acc[mt][ne][1], acc[mt][ne][2], acc[mt][ne][3],
                      a_cur[mt], b_cur[npl].x, b_cur[npl].y);
                mma16(acc[mt][no][0], acc[mt][no][1], acc[mt][no][2], acc[mt][no][3],
                      a_cur[mt], b_cur[npl].z, b_cur[npl].w);
            }
        }
        if (f < 7) {
#pragma unroll
            for (int mt = 0; mt < 4; ++mt) a_cur[mt] = a_nxt[mt];
#pragma unroll
            for (int npl = 0; npl < 4; ++npl) b_cur[npl] = b_nxt[npl];
        }
    }
}

// Prefetch one 16KB B stage (4 cp16/thread at 256 threads).
static __device__ __forceinline__ void prefetch_stage(uint32_t sb, int tid, int g,
                                                      uint32_t slotoff) {
    const uint4* bs = g_bt + (size_t)g * 1024;
#pragma unroll
    for (int i = 0; i < 4; ++i)
        cp16(sb + B_OFF + slotoff + (uint32_t)(i * 256 + tid) * 16, bs + i * 256 + tid);
}

// ---------------------------------------------------------------------------
// Main: A-pack prologue + pipelined fp16 GEMM + magic-key top-2 +
// confident-token gather tail. 256 threads, 8 warps 4(M) x 2(N).
__global__ __launch_bounds__(256, 1) void vq_mma_kernel(const float* __restrict__ x,
                                                        const float* __restrict__ embed,
                                                        float* __restrict__ out_q,
                                                        float* __restrict__ out_i) {
    extern __shared__ char sm[];
    const uint32_t sb = smem_u32(sm);
    const int tid = threadIdx.x, lane = tid & 31, wid = tid >> 5;
    const int warpM = wid & 3, warpN = wid >> 2;   // 4 x 2
    const int cta = blockIdx.x;
    const int t0 = cta * 256;

    // ---- Prologue: cesc + B stages 0,1 (one async group) ----
    {
        const uint4* es = (const uint4*)g_cesc;
#pragma unroll
        for (int i = 0; i < 4; ++i)
            cp16(sb + ESQ_OFF + (uint32_t)(i * 256 + tid) * 16, es + i * 256 + tid);
        prefetch_stage(sb, tid, 0, 0);
        prefetch_stage(sb, tid, 1, 16384);
        CP_COMMIT();
    }

    // A: fp16 fragments straight from global x (32 units/thread).
#pragma unroll
    for (int it = 0; it < 32; ++it) {
        int u = it * 256 + tid;
        int mtl = u >> 9, kt = (u >> 5) & 15, ln = u & 31;
        int r = mtl * 16 + (ln >> 2), c = kt * 16 + (ln & 3) * 2;
        const float* p = x + ((size_t)t0 + r) * D_DIM + c;
        float2 v00 = __ldg((const float2*)p);
        float2 v80 = __ldg((const float2*)(p + 8 * D_DIM));
        float2 v08 = __ldg((const float2*)(p + 8));
        float2 v88 = __ldg((const float2*)(p + 8 * D_DIM + 8));
        uint4 q;
        q.x = h2pack(v00.x, v00.y);
        q.y = h2pack(v80.x, v80.y);
        q.z = h2pack(v08.x, v08.y);
        q.w = h2pack(v88.x, v88.y);
        *(uint4*)(sm + A_OFF + (uint32_t)((mtl * 16 + kt) * 32 + ln) * 16) = q;
    }

    float acc[4][8][4];
#pragma unroll
    for (int mt = 0; mt < 4; ++mt)
#pragma unroll
        for (int nt = 0; nt < 8; ++nt)
#pragma unroll
            for (int c = 0; c < 4; ++c) acc[mt][nt][c] = 0.f;

    uint32_t k1[8], k2[8];
#pragma unroll
    for (int s = 0; s < 8; ++s) { k1[s] = 0u; k2[s] = 0u; }

    const float* cesm = (const float*)(sm + ESQ_OFF);
    const int eb = warpN * 64 + (lane & 3) * 2;   // chunk-invariant epilogue base

    for (int GG = 0; GG < 32; ++GG) {
        // Group A: compute slots 0/1 (ktiles 0-7); prefetch into 2/3.
        CP_WAIT(0);
        __syncthreads();
        prefetch_stage(sb, tid, 4 * GG + 2, 32768);
        prefetch_stage(sb, tid, 4 * GG + 3, 49152);
        CP_COMMIT();
        group_mma<0, 0>(sm, warpM, warpN, lane, acc);

        // Group B: compute slots 2/3 (ktiles 8-15); prefetch into 0/1.
        CP_WAIT(0);
        __syncthreads();
        if (GG < 31) {
            prefetch_stage(sb, tid, 4 * GG + 4, 0);
            prefetch_stage(sb, tid, 4 * GG + 5, 16384);
            CP_COMMIT();
        }
        group_mma<2, 8>(sm, warpM, warpN, lane, acc);

        // Epilogue: chunk GG complete.
        // w3 = (2*dot + 16 - esq)*KSCALE + 2^23; mantissa = 20-bit fixed point.
        // key = bits(w3)*4096 + (binv - idx)  — exponent shifts out mod 2^32.
        {
            int n0 = GG * 128 + eb;
            uint32_t binv = 4095u - (uint32_t)n0;
            float2 cz[8];
#pragma unroll
            for (int nt = 0; nt < 8; ++nt)
                cz[nt] = *(const float2*)(cesm + n0 + nt * 8);
#pragma unroll
            for (int mt = 0; mt < 4; ++mt)
#pragma unroll
                for (int nt = 0; nt < 8; ++nt)
#pragma unroll
                    for (int c = 0; c < 4; ++c) {
                        float cesc = (c & 1) ? cz[nt].y : cz[nt].x;
                        float w3 = fmaf(2.0f * KSCALE, acc[mt][nt][c], cesc);
                        acc[mt][nt][c] = 0.f;
                        uint32_t key = __float_as_uint(w3) * 4096u +
                                       (binv - (uint32_t)(nt * 8 + (c & 1)));
                        const int s = mt * 2 + (c >> 1);
                        uint32_t km = umin(k1[s], key);
                        k1[s] = umax(k1[s], key);
                        k2[s] = umax(k2[s], km);
                    }
        }
    }

    // ---- Tail: keys -> SMEM (dead ring slot 0) + g_ckey (for rescue) ----
    __syncthreads();
    uint32_t* skeys = (uint32_t*)(sm + B_OFF);   // 256 tokens x 16 keys = 16KB
#pragma unroll
    for (int s = 0; s < 8; ++s) {
        int mt = s >> 1, ch = s & 1;
        int row = warpM * 64 + mt * 16 + ch * 8 + (lane >> 2);
        int slot = (warpN * 4 + (lane & 3)) * 2;
        uint2 kk2 = make_uint2(k1[s], k2[s]);
        *(uint2*)(skeys + row * 16 + slot) = kk2;
        *(uint2*)(g_ckey + ((size_t)t0 + row) * 16 + slot) = kk2;
    }
    __syncthreads();

    // ---- Confident-token merge + gather (warp per token, 32 tokens/warp) ----
    for (int it = 0; it < 32; ++it) {
        const int t = wid * 32 + it;
        const int tg = t0 + t;
        uint32_t key = (lane < 16) ? skeys[t * 16 + lane] : 0u;

        uint32_t kb = key;
#pragma unroll
        for (int off = 16; off > 0; off >>= 1)
            kb = umax(kb, __shfl_xor_sync(0xffffffffu, kb, off));
        uint32_t ex = (key == kb) ? 0u : key;
#pragma unroll
        for (int off = 16; off > 0; off >>= 1)
            ex = umax(ex, __shfl_xor_sync(0xffffffffu, ex, off));

        float v1 = (float)(kb >> 12) * (1.0f / KSCALE);
        float v2 = (float)(ex >> 12) * (1.0f / KSCALE);

        if (v1 - v2 >= EPS_GAP) {
            int best = 4095 - (int)(kb & 0xFFFu);
            const float4* src = (const float4*)(embed + (size_t)best * D_DIM);
            float4* dst = (float4*)(out_q + (size_t)tg * D_DIM);
            dst[lane] = src[lane];
            dst[lane + 32] = src[lane + 32];
            if (lane == 0 && out_i) out_i[tg] = (float)best;
        }
    }
}

// ---------------------------------------------------------------------------
// Rescue: recheck gap; early-exit for confident tokens (already written);
// exact fp32 rescore + gather for the rare ambiguous ones (16 candidates).
__global__ __launch_bounds__(256) void rescue_kernel(const float* __restrict__ x,
                                                     const float* __restrict__ embed,
                                                     float* __restrict__ out_q,
                                                     float* __restrict__ out_i) {
    const int lane = threadIdx.x & 31, wid = threadIdx.x >> 5;
    const int t = blockIdx.x * 8 + wid;

    uint32_t key = (lane < 16) ? g_ckey[(size_t)t * 16 + lane] : 0u;

    uint32_t kb = key;
#pragma unroll
    for (int off = 16; off > 0; off >>= 1)
        kb = umax(kb, __shfl_xor_sync(0xffffffffu, kb, off));
    uint32_t ex = (key == kb) ? 0u : key;
#pragma unroll
    for (int off = 16; off > 0; off >>= 1)
        ex = umax(ex, __shfl_xor_sync(0xffffffffu, ex, off));

    float v1 = (float)(kb >> 12) * (1.0f / KSCALE);
    float v2 = (float)(ex >> 12) * (1.0f / KSCALE);
    if (v1 - v2 >= EPS_GAP) return;   // warp-uniform: main already wrote it

    const float* xr = x + (size_t)t * D_DIM;
    float xv[8];
#pragma unroll
    for (int j = 0; j < 8; ++j) xv[j] = xr[lane + 32 * j];

    float p = 0.f;
#pragma unroll
    for (int j = 0; j < 8; ++j)
        p = __fadd_rn(p, __fmul_rn(xv[j], xv[j]));
#pragma unroll
    for (int off = 16; off > 0; off >>= 1)
        p = __fadd_rn(p, __shfl_xor_sync(0xffffffffu, p, off));
    const float xsq = p;

    int cand = 4095 - (int)(key & 0xFFFu);
    float bv = -FLT_MAX; int bi = 0x7fffffff;
    for (int c = 0; c < 16; ++c) {
        int idc = __shfl_sync(0xffffffffu, cand, c);
        const float* er = embed + (size_t)idc * D_DIM;
        float d = 0.f;
#pragma unroll
        for (int j = 0; j < 8; ++j)
            d = fmaf(xv[j], er[lane + 32 * j], d);
#pragma unroll
        for (int off = 16; off > 0; off >>= 1)
            d += __shfl_xor_sync(0xffffffffu, d, off);
        float t2v = __fsub_rn(xsq, __fmul_rn(2.f, d));
        float dn = -__fadd_rn(t2v, g_esq[idc]);
        if (dn > bv || (dn == bv && idc < bi)) { bv = dn; bi = idc; }
    }

    const float4* src = (const float4*)(embed + (size_t)bi * D_DIM);
    float4* dst = (float4*)(out_q + (size_t)t * D_DIM);
    dst[lane] = src[lane];
    dst[lane + 32] = src[lane + 32];
    if (lane == 0 && out_i) out_i[t] = (float)bi;
}

// ---------------------------------------------------------------------------
extern "C" void kernel_launch(void* const* d_in, const int* in_sizes, int n_in,
                              void* d_out, int out_size) {
    const float* x     = (const float*)d_in[0];
    const float* embed = (const float*)d_in[1];

    int T = in_sizes[2];  // 32768

    float* outq = (float*)d_out;
    float* outi = nullptr;
    if ((long long)out_size >= (long long)T * D_DIM + T)
        outi = outq + (size_t)T * D_DIM;

    prep_kernel<<<(128 * 1024) / 256, 256>>>(embed);

    cudaFuncSetAttribute(vq_mma_kernel,
                         cudaFuncAttributeMaxDynamicSharedMemorySize, SMEM_BYTES);
    vq_mma_kernel<<<T / 256, 256, SMEM_BYTES>>>(x, embed, outq, outi);

    rescue_kernel<<<T / 8, 256>>>(x, embed, outq, outi);
}